// round 15
// baseline (speedup 1.0000x reference)
#include <cuda_runtime.h>
#include <cuda_fp16.h>
#include <math.h>

#define NMAX 100000
#define EMAX 1600000
#define KDIM 128

// ---------------- scratch (static device globals; no allocation) ------------
__device__ __align__(16) __half d_g1[(size_t)NMAX * 128]; // x@W1  (fp16, gathered)
__device__ __align__(16) __half d_h1[(size_t)NMAX * 128]; // layer-1 out (fp16)
__device__ __align__(16) __half d_g2[(size_t)NMAX * 64];  // h1@W2 (fp16, gathered)
__device__ float d_dinv[NMAX];
__device__ int   d_counts[NMAX];
__device__ int   d_offsets[NMAX];
__device__ int   d_cursor[NMAX];
__device__ int   d_bsum[128];
__device__ int   d_bpre[128];
__device__ __align__(16) int2 d_edge[EMAX + 16]; // (src, bitcast wgt); padded

// ---------------- CSR build -------------------------------------------------
__global__ void k_count(const int* __restrict__ ei, int E) {
    int e = blockIdx.x * blockDim.x + threadIdx.x;
    if (e < E) atomicAdd(&d_counts[ei[(size_t)E + e]], 1);
}

__global__ void k_scan_local(int n) {
    __shared__ int wsum[32];
    int i    = blockIdx.x * 1024 + threadIdx.x;
    int lane = threadIdx.x & 31;
    int wid  = threadIdx.x >> 5;
    int v = (i < n) ? d_counts[i] : 0;
    int x = v;
    #pragma unroll
    for (int d = 1; d < 32; d <<= 1) {
        int t = __shfl_up_sync(0xffffffffu, x, d);
        if (lane >= d) x += t;
    }
    if (lane == 31) wsum[wid] = x;
    __syncthreads();
    if (wid == 0) {
        int s = wsum[lane];
        #pragma unroll
        for (int d = 1; d < 32; d <<= 1) {
            int t = __shfl_up_sync(0xffffffffu, s, d);
            if (lane >= d) s += t;
        }
        wsum[lane] = s;
    }
    __syncthreads();
    int warp_prefix = (wid > 0) ? wsum[wid - 1] : 0;
    if (i < n) {
        d_offsets[i] = warp_prefix + x - v;
        d_dinv[i]    = rsqrtf((float)(1 + v));
    }
    if (threadIdx.x == 1023) d_bsum[blockIdx.x] = warp_prefix + x;
}

__global__ void k_scan_bsum(int nb) {
    __shared__ int wsum[4];
    int lane = threadIdx.x & 31;
    int wid  = threadIdx.x >> 5;
    int v = (threadIdx.x < nb) ? d_bsum[threadIdx.x] : 0;
    int x = v;
    #pragma unroll
    for (int d = 1; d < 32; d <<= 1) {
        int t = __shfl_up_sync(0xffffffffu, x, d);
        if (lane >= d) x += t;
    }
    if (lane == 31) wsum[wid] = x;
    __syncthreads();
    int wp = 0;
    for (int k = 0; k < wid; k++) wp += wsum[k];
    if (threadIdx.x < nb) d_bpre[threadIdx.x] = wp + x - v;
}

__global__ void k_scan_apply(int n) {
    int i = blockIdx.x * blockDim.x + threadIdx.x;
    if (i < n) {
        int off = d_offsets[i] + d_bpre[i >> 10];
        d_offsets[i] = off;
        d_cursor[i]  = off;
    }
}

__global__ void k_fill(const int* __restrict__ ei, int E) {
    int e = blockIdx.x * blockDim.x + threadIdx.x;
    if (e < E) {
        int src = ei[e];
        int dst = ei[(size_t)E + e];
        int p = atomicAdd(&d_cursor[dst], 1);
        float wgt = d_dinv[src] * d_dinv[dst];
        d_edge[p] = make_int2(src, __float_as_int(wgt));
    }
}

// -------- tf32 tensor-core GEMM: G(half) = A[rows,128] @ W[128,BN] ----------
__device__ __forceinline__ float to_tf32(float x) {
    float r;
    asm("cvt.rna.tf32.f32 %0, %1;" : "=f"(r) : "f"(x));
    return r;
}

template <int BM, int BN, typename AT>
__global__ void __launch_bounds__(BM * 2)
k_gemm_tc(const AT* __restrict__ A, const float* __restrict__ W,
          __half* __restrict__ G, int rbase, int rend) {
    constexpr int K  = KDIM;
    constexpr int NT = BM * 2;
    constexpr int SA = 132;
    constexpr int SB = BN + 8;
    constexpr int NTI = BN / 8;

    extern __shared__ float sm[];
    float* As = sm;                  // [BM][SA]
    float* Ws = sm + BM * SA;        // [K][SB]

    const int tid = threadIdx.x;
    const int r0  = rbase + blockIdx.x * BM;

    if constexpr (sizeof(AT) == 4) {
        #pragma unroll
        for (int it = 0; it < (BM * (K / 4)) / NT; it++) {
            int i   = tid + it * NT;
            int row = i >> 5;
            int c4  = i & 31;
            float4 v = make_float4(0.f, 0.f, 0.f, 0.f);
            if (r0 + row < rend)  // streaming read-once: evict-first
                v = __ldcs(reinterpret_cast<const float4*>((const float*)A + (size_t)(r0 + row) * K + c4 * 4));
            float* p = As + row * SA + c4 * 4;
            p[0] = to_tf32(v.x); p[1] = to_tf32(v.y);
            p[2] = to_tf32(v.z); p[3] = to_tf32(v.w);
        }
    } else {
        #pragma unroll
        for (int it = 0; it < (BM * (K / 8)) / NT; it++) {
            int i   = tid + it * NT;
            int row = i >> 4;
            int c8  = i & 15;
            uint4 v = make_uint4(0u, 0u, 0u, 0u);
            if (r0 + row < rend)  // streaming read-once: evict-first
                v = __ldcs(reinterpret_cast<const uint4*>((const __half*)A + (size_t)(r0 + row) * K + c8 * 8));
            float2 f0 = __half22float2(*reinterpret_cast<__half2*>(&v.x));
            float2 f1 = __half22float2(*reinterpret_cast<__half2*>(&v.y));
            float2 f2 = __half22float2(*reinterpret_cast<__half2*>(&v.z));
            float2 f3 = __half22float2(*reinterpret_cast<__half2*>(&v.w));
            float* p = As + row * SA + c8 * 8;
            p[0] = to_tf32(f0.x); p[1] = to_tf32(f0.y);
            p[2] = to_tf32(f1.x); p[3] = to_tf32(f1.y);
            p[4] = to_tf32(f2.x); p[5] = to_tf32(f2.y);
            p[6] = to_tf32(f3.x); p[7] = to_tf32(f3.y);
        }
    }
    #pragma unroll
    for (int it = 0; it < (K * (BN / 4)) / NT; it++) {
        int i   = tid + it * NT;
        int row = i / (BN / 4);
        int c4  = i % (BN / 4);
        float4 v = *reinterpret_cast<const float4*>(W + (size_t)row * BN + c4 * 4);
        float* p = Ws + row * SB + c4 * 4;
        p[0] = to_tf32(v.x); p[1] = to_tf32(v.y);
        p[2] = to_tf32(v.z); p[3] = to_tf32(v.w);
    }
    __syncthreads();

    const int warp = tid >> 5;
    const int lane = tid & 31;
    const int g    = lane >> 2;
    const int tg   = lane & 3;
    const int wr   = warp * 16;

    float acc[NTI][4];
    #pragma unroll
    for (int nt = 0; nt < NTI; nt++) {
        acc[nt][0] = 0.f; acc[nt][1] = 0.f; acc[nt][2] = 0.f; acc[nt][3] = 0.f;
    }

    #pragma unroll
    for (int kc = 0; kc < K / 8; kc++) {
        int c = kc * 8 + tg;
        float a0 = As[(wr + g)     * SA + c];
        float a1 = As[(wr + g + 8) * SA + c];
        float a2 = As[(wr + g)     * SA + c + 4];
        float a3 = As[(wr + g + 8) * SA + c + 4];
        #pragma unroll
        for (int nt = 0; nt < NTI; nt++) {
            float b0 = Ws[c       * SB + nt * 8 + g];
            float b1 = Ws[(c + 4) * SB + nt * 8 + g];
            asm volatile(
                "mma.sync.aligned.m16n8k8.row.col.f32.tf32.tf32.f32 "
                "{%0,%1,%2,%3}, {%4,%5,%6,%7}, {%8,%9}, {%0,%1,%2,%3};"
                : "+f"(acc[nt][0]), "+f"(acc[nt][1]),
                  "+f"(acc[nt][2]), "+f"(acc[nt][3])
                : "r"(__float_as_uint(a0)), "r"(__float_as_uint(a1)),
                  "r"(__float_as_uint(a2)), "r"(__float_as_uint(a3)),
                  "r"(__float_as_uint(b0)), "r"(__float_as_uint(b1)));
        }
    }

    int rowA = r0 + wr + g;
    int rowB = rowA + 8;
    #pragma unroll
    for (int nt = 0; nt < NTI; nt++) {
        int col = nt * 8 + 2 * tg;
        if (rowA < rend)
            *reinterpret_cast<__half2*>(G + (size_t)rowA * BN + col) =
                __float22half2_rn(make_float2(acc[nt][0], acc[nt][1]));
        if (rowB < rend)
            *reinterpret_cast<__half2*>(G + (size_t)rowB * BN + col) =
                __float22half2_rn(make_float2(acc[nt][2], acc[nt][3]));
    }
}

// ---- aggregation (R9 form + streaming hints, node range) --------------------
// out[i] = relu(Σ wgt·g[src] + dinv²·g[i] + b)
template <int F, typename OutT>
__global__ void __launch_bounds__(256)
k_agg(const __half* __restrict__ g, const float* __restrict__ bias,
      OutT* __restrict__ out, int nbase, int nend) {
    constexpr int V = F / 32;          // halfs per lane (4 or 2)
    int w = nbase + ((blockIdx.x * blockDim.x + threadIdx.x) >> 5);
    if (w >= nend) return;
    int lane = threadIdx.x & 31;

    float dv  = d_dinv[w];
    float dv2 = dv * dv;
    float acc[V];
    const __half* self = g + (size_t)w * F + lane * V;
    if constexpr (V == 4) {
        uint2 r = *reinterpret_cast<const uint2*>(self);
        float2 s0 = __half22float2(*reinterpret_cast<__half2*>(&r.x));
        float2 s1 = __half22float2(*reinterpret_cast<__half2*>(&r.y));
        acc[0] = s0.x * dv2; acc[1] = s0.y * dv2;
        acc[2] = s1.x * dv2; acc[3] = s1.y * dv2;
    } else {
        float2 s0 = __half22float2(*reinterpret_cast<const __half2*>(self));
        acc[0] = s0.x * dv2; acc[1] = s0.y * dv2;
    }

    int start = d_offsets[w];
    int cnt   = d_counts[w];
    for (int j = 0; j < cnt; j += 8) {
        int2 ew[8];
        #pragma unroll
        for (int u = 0; u < 8; u++) ew[u] = __ldcs(&d_edge[start + j + u]);
        int   idx[8];
        float wf[8];
        #pragma unroll
        for (int u = 0; u < 8; u++) {
            bool ok = (j + u) < cnt;
            idx[u] = ok ? ew[u].x : w;
            wf[u]  = ok ? __int_as_float(ew[u].y) : 0.f;
        }
        if constexpr (V == 4) {
            uint2 t[8];
            #pragma unroll
            for (int u = 0; u < 8; u++)
                t[u] = *reinterpret_cast<const uint2*>(g + (size_t)idx[u] * F + lane * 4);
            #pragma unroll
            for (int u = 0; u < 8; u++) {
                float2 f0 = __half22float2(*reinterpret_cast<__half2*>(&t[u].x));
                float2 f1 = __half22float2(*reinterpret_cast<__half2*>(&t[u].y));
                acc[0] += f0.x * wf[u]; acc[1] += f0.y * wf[u];
                acc[2] += f1.x * wf[u]; acc[3] += f1.y * wf[u];
            }
        } else {
            unsigned t[8];
            #pragma unroll
            for (int u = 0; u < 8; u++)
                t[u] = *reinterpret_cast<const unsigned*>(g + (size_t)idx[u] * F + lane * 2);
            #pragma unroll
            for (int u = 0; u < 8; u++) {
                float2 f0 = __half22float2(*reinterpret_cast<__half2*>(&t[u]));
                acc[0] += f0.x * wf[u]; acc[1] += f0.y * wf[u];
            }
        }
    }

    float r[V];
    #pragma unroll
    for (int v = 0; v < V; v++) {
        float val = acc[v] + __ldg(&bias[lane * V + v]);
        r[v] = val > 0.f ? val : 0.f;
    }
    if constexpr (sizeof(OutT) == 4) {
        float* o = (float*)out + (size_t)w * F + lane * V;
        if constexpr (V == 4)
            __stcs(reinterpret_cast<float4*>(o), make_float4(r[0], r[1], r[2], r[3]));
        else
            __stcs(reinterpret_cast<float2*>(o), make_float2(r[0], r[1]));
    } else {
        __half* o = (__half*)out + (size_t)w * F + lane * V;
        if constexpr (V == 4) {
            uint2 p;
            *reinterpret_cast<__half2*>(&p.x) = __float22half2_rn(make_float2(r[0], r[1]));
            *reinterpret_cast<__half2*>(&p.y) = __float22half2_rn(make_float2(r[2], r[3]));
            __stcs(reinterpret_cast<uint2*>(o), p);
        } else {
            __half2 p = __float22half2_rn(make_float2(r[0], r[1]));
            __stcs(reinterpret_cast<unsigned*>(o), *reinterpret_cast<unsigned*>(&p));
        }
    }
}

// ---------------- launch -----------------------------------------------------
extern "C" void kernel_launch(void* const* d_in, const int* in_sizes, int n_in,
                              void* d_out, int out_size) {
    const float* x  = (const float*)d_in[0];
    const int*   ei = (const int*)d_in[1];
    const float* W1 = (const float*)d_in[2];
    const float* b1 = (const float*)d_in[3];
    const float* W2 = (const float*)d_in[4];
    const float* b2 = (const float*)d_in[5];
    float* out = (float*)d_out;

    const int M = in_sizes[0] / 128;  // 100000 nodes
    const int E = in_sizes[1] / 2;    // 1600000 edges

    constexpr int SMEM1 = (128 * 132 + 128 * (128 + 8)) * 4;  // 137216
    constexpr int SMEM2 = (64 * 132  + 128 * (64 + 8))  * 4;  // 70656

    __half *g1, *h1, *g2;
    int* counts;
    cudaGetSymbolAddress((void**)&g1, d_g1);
    cudaGetSymbolAddress((void**)&h1, d_h1);
    cudaGetSymbolAddress((void**)&g2, d_g2);
    cudaGetSymbolAddress((void**)&counts, d_counts);

    // one-time resource setup (identical captured graph every call)
    static cudaStream_t s1 = nullptr;
    static cudaEvent_t eFork = nullptr, eCsr = nullptr,
                       eA0 = nullptr, eA1 = nullptr, eB = nullptr;
    if (!s1) {
        cudaStreamCreateWithFlags(&s1, cudaStreamNonBlocking);
        cudaEventCreateWithFlags(&eFork, cudaEventDisableTiming);
        cudaEventCreateWithFlags(&eCsr,  cudaEventDisableTiming);
        cudaEventCreateWithFlags(&eA0,   cudaEventDisableTiming);
        cudaEventCreateWithFlags(&eA1,   cudaEventDisableTiming);
        cudaEventCreateWithFlags(&eB,    cudaEventDisableTiming);
        cudaFuncSetAttribute((const void*)k_gemm_tc<128, 128, float>,
                             cudaFuncAttributeMaxDynamicSharedMemorySize, SMEM1);
        cudaFuncSetAttribute((const void*)k_gemm_tc<64, 64, __half>,
                             cudaFuncAttributeMaxDynamicSharedMemorySize, SMEM2);
    }

    const int nblk = (M + 1023) / 1024;
    const int M2   = ((M / 2 + 63) / 64) * 64;   // chunk split, 64-aligned

    // fork: CSR build on s1 runs concurrently with GEMM1 on s0
    cudaEventRecord(eFork, 0);
    cudaStreamWaitEvent(s1, eFork, 0);

    cudaMemsetAsync(counts, 0, (size_t)M * sizeof(int), s1);
    k_count<<<(E + 255) / 256, 256, 0, s1>>>(ei, E);
    k_scan_local<<<nblk, 1024, 0, s1>>>(M);
    k_scan_bsum <<<1, 128, 0, s1>>>(nblk);
    k_scan_apply<<<(M + 255) / 256, 256, 0, s1>>>(M);
    k_fill <<<(E + 255) / 256, 256, 0, s1>>>(ei, E);
    cudaEventRecord(eCsr, s1);

    k_gemm_tc<128, 128, float><<<(M + 127) / 128, 256, SMEM1>>>(x, W1, g1, 0, M);

    cudaStreamWaitEvent(0, eCsr, 0);   // join before agg1

    // --- pipelined: agg1 chunk c on s0, GEMM2 chunk c on s1 ---
    k_agg<128, __half><<<((M2 * 32) + 255) / 256, 256>>>(g1, b1, h1, 0, M2);
    cudaEventRecord(eA0, 0);
    cudaStreamWaitEvent(s1, eA0, 0);
    k_gemm_tc<64, 64, __half><<<(M2 + 63) / 64, 128, SMEM2, s1>>>(h1, W2, g2, 0, M2);

    k_agg<128, __half><<<(((M - M2) * 32) + 255) / 256, 256>>>(g1, b1, h1, M2, M);
    cudaEventRecord(eA1, 0);
    cudaStreamWaitEvent(s1, eA1, 0);
    k_gemm_tc<64, 64, __half><<<(M - M2 + 63) / 64, 128, SMEM2, s1>>>(h1, W2, g2, M2, M);
    cudaEventRecord(eB, s1);
    cudaStreamWaitEvent(0, eB, 0);     // join: all g2 ready

    k_agg<64, float><<<((M * 32) + 255) / 256, 256>>>(g2, b2, out, 0, M);
}

// round 16
// speedup vs baseline: 1.0232x; 1.0232x over previous
#include <cuda_runtime.h>
#include <cuda_fp16.h>
#include <math.h>

#define NMAX 100000
#define EMAX 1600000
#define KDIM 128

// ---------------- scratch (static device globals; no allocation) ------------
__device__ __align__(16) __half d_g1[(size_t)NMAX * 128]; // x@W1  (fp16, gathered)
__device__ __align__(16) __half d_h1[(size_t)NMAX * 128]; // layer-1 out (fp16)
__device__ __align__(16) __half d_g2[(size_t)NMAX * 64];  // h1@W2 (fp16, gathered)
__device__ float d_dinv[NMAX];
__device__ int   d_counts[NMAX];
__device__ int   d_offsets[NMAX];   // block-LOCAL offsets (add d_bpre[i>>10])
__device__ int   d_cursor[NMAX];    // block-LOCAL cursors
__device__ int   d_bsum[128];
__device__ int   d_bpre[128];
__device__ __align__(16) int2 d_edge[EMAX + 16]; // (src, bitcast wgt); padded

// ---------------- CSR build -------------------------------------------------
// 4 edges per thread via int4 loads of the dst row
__global__ void k_count(const int* __restrict__ ei, int E) {
    int e4 = (blockIdx.x * blockDim.x + threadIdx.x) * 4;
    if (e4 + 3 < E) {
        int4 d = *reinterpret_cast<const int4*>(ei + (size_t)E + e4);
        atomicAdd(&d_counts[d.x], 1);
        atomicAdd(&d_counts[d.y], 1);
        atomicAdd(&d_counts[d.z], 1);
        atomicAdd(&d_counts[d.w], 1);
    } else {
        for (int e = e4; e < E; e++)
            atomicAdd(&d_counts[ei[(size_t)E + e]], 1);
    }
}

// stage 1: per-block (1024) local exclusive scan + dinv; cursor = local offset
__global__ void k_scan_local(int n) {
    __shared__ int wsum[32];
    int i    = blockIdx.x * 1024 + threadIdx.x;
    int lane = threadIdx.x & 31;
    int wid  = threadIdx.x >> 5;
    int v = (i < n) ? d_counts[i] : 0;
    int x = v;
    #pragma unroll
    for (int d = 1; d < 32; d <<= 1) {
        int t = __shfl_up_sync(0xffffffffu, x, d);
        if (lane >= d) x += t;
    }
    if (lane == 31) wsum[wid] = x;
    __syncthreads();
    if (wid == 0) {
        int s = wsum[lane];
        #pragma unroll
        for (int d = 1; d < 32; d <<= 1) {
            int t = __shfl_up_sync(0xffffffffu, s, d);
            if (lane >= d) s += t;
        }
        wsum[lane] = s;
    }
    __syncthreads();
    int warp_prefix = (wid > 0) ? wsum[wid - 1] : 0;
    if (i < n) {
        int loc = warp_prefix + x - v;
        d_offsets[i] = loc;               // local
        d_cursor[i]  = loc;               // local
        d_dinv[i]    = rsqrtf((float)(1 + v));
    }
    if (threadIdx.x == 1023) d_bsum[blockIdx.x] = warp_prefix + x;
}

// stage 2: scan the (<=128) block totals
__global__ void k_scan_bsum(int nb) {
    __shared__ int wsum[4];
    int lane = threadIdx.x & 31;
    int wid  = threadIdx.x >> 5;
    int v = (threadIdx.x < nb) ? d_bsum[threadIdx.x] : 0;
    int x = v;
    #pragma unroll
    for (int d = 1; d < 32; d <<= 1) {
        int t = __shfl_up_sync(0xffffffffu, x, d);
        if (lane >= d) x += t;
    }
    if (lane == 31) wsum[wid] = x;
    __syncthreads();
    int wp = 0;
    for (int k = 0; k < wid; k++) wp += wsum[k];
    if (threadIdx.x < nb) d_bpre[threadIdx.x] = wp + x - v;
}

// fill: 4 edges per thread (int4 src + int4 dst); global pos = local + bpre
__global__ void k_fill(const int* __restrict__ ei, int E) {
    int e4 = (blockIdx.x * blockDim.x + threadIdx.x) * 4;
    if (e4 + 3 < E) {
        int4 s = *reinterpret_cast<const int4*>(ei + e4);
        int4 d = *reinterpret_cast<const int4*>(ei + (size_t)E + e4);
        int src[4] = {s.x, s.y, s.z, s.w};
        int dst[4] = {d.x, d.y, d.z, d.w};
        #pragma unroll
        for (int u = 0; u < 4; u++) {
            int p = atomicAdd(&d_cursor[dst[u]], 1) + d_bpre[dst[u] >> 10];
            float wgt = d_dinv[src[u]] * d_dinv[dst[u]];
            d_edge[p] = make_int2(src[u], __float_as_int(wgt));
        }
    } else {
        for (int e = e4; e < E; e++) {
            int src = ei[e];
            int dst = ei[(size_t)E + e];
            int p = atomicAdd(&d_cursor[dst], 1) + d_bpre[dst >> 10];
            float wgt = d_dinv[src] * d_dinv[dst];
            d_edge[p] = make_int2(src, __float_as_int(wgt));
        }
    }
}

// -------- tf32 tensor-core GEMM: G(half) = A[M,128] @ W[128,BN] -------------
__device__ __forceinline__ float to_tf32(float x) {
    float r;
    asm("cvt.rna.tf32.f32 %0, %1;" : "=f"(r) : "f"(x));
    return r;
}

template <int BM, int BN, typename AT>
__global__ void __launch_bounds__(BM * 2)
k_gemm_tc(const AT* __restrict__ A, const float* __restrict__ W,
          __half* __restrict__ G, int M) {
    constexpr int K  = KDIM;
    constexpr int NT = BM * 2;
    constexpr int SA = 132;
    constexpr int SB = BN + 8;
    constexpr int NTI = BN / 8;

    extern __shared__ float sm[];
    float* As = sm;                  // [BM][SA]
    float* Ws = sm + BM * SA;        // [K][SB]

    const int tid = threadIdx.x;
    const int r0  = blockIdx.x * BM;

    if constexpr (sizeof(AT) == 4) {
        #pragma unroll
        for (int it = 0; it < (BM * (K / 4)) / NT; it++) {
            int i   = tid + it * NT;
            int row = i >> 5;
            int c4  = i & 31;
            float4 v = make_float4(0.f, 0.f, 0.f, 0.f);
            if (r0 + row < M)   // streaming read-once: evict-first
                v = __ldcs(reinterpret_cast<const float4*>((const float*)A + (size_t)(r0 + row) * K + c4 * 4));
            float* p = As + row * SA + c4 * 4;
            p[0] = to_tf32(v.x); p[1] = to_tf32(v.y);
            p[2] = to_tf32(v.z); p[3] = to_tf32(v.w);
        }
    } else {
        #pragma unroll
        for (int it = 0; it < (BM * (K / 8)) / NT; it++) {
            int i   = tid + it * NT;
            int row = i >> 4;
            int c8  = i & 15;
            uint4 v = make_uint4(0u, 0u, 0u, 0u);
            if (r0 + row < M)   // streaming read-once: evict-first
                v = __ldcs(reinterpret_cast<const uint4*>((const __half*)A + (size_t)(r0 + row) * K + c8 * 8));
            float2 f0 = __half22float2(*reinterpret_cast<__half2*>(&v.x));
            float2 f1 = __half22float2(*reinterpret_cast<__half2*>(&v.y));
            float2 f2 = __half22float2(*reinterpret_cast<__half2*>(&v.z));
            float2 f3 = __half22float2(*reinterpret_cast<__half2*>(&v.w));
            float* p = As + row * SA + c8 * 8;
            p[0] = to_tf32(f0.x); p[1] = to_tf32(f0.y);
            p[2] = to_tf32(f1.x); p[3] = to_tf32(f1.y);
            p[4] = to_tf32(f2.x); p[5] = to_tf32(f2.y);
            p[6] = to_tf32(f3.x); p[7] = to_tf32(f3.y);
        }
    }
    #pragma unroll
    for (int it = 0; it < (K * (BN / 4)) / NT; it++) {
        int i   = tid + it * NT;
        int row = i / (BN / 4);
        int c4  = i % (BN / 4);
        float4 v = *reinterpret_cast<const float4*>(W + (size_t)row * BN + c4 * 4);
        float* p = Ws + row * SB + c4 * 4;
        p[0] = to_tf32(v.x); p[1] = to_tf32(v.y);
        p[2] = to_tf32(v.z); p[3] = to_tf32(v.w);
    }
    __syncthreads();

    const int warp = tid >> 5;
    const int lane = tid & 31;
    const int g    = lane >> 2;
    const int tg   = lane & 3;
    const int wr   = warp * 16;

    float acc[NTI][4];
    #pragma unroll
    for (int nt = 0; nt < NTI; nt++) {
        acc[nt][0] = 0.f; acc[nt][1] = 0.f; acc[nt][2] = 0.f; acc[nt][3] = 0.f;
    }

    #pragma unroll
    for (int kc = 0; kc < K / 8; kc++) {
        int c = kc * 8 + tg;
        float a0 = As[(wr + g)     * SA + c];
        float a1 = As[(wr + g + 8) * SA + c];
        float a2 = As[(wr + g)     * SA + c + 4];
        float a3 = As[(wr + g + 8) * SA + c + 4];
        #pragma unroll
        for (int nt = 0; nt < NTI; nt++) {
            float b0 = Ws[c       * SB + nt * 8 + g];
            float b1 = Ws[(c + 4) * SB + nt * 8 + g];
            asm volatile(
                "mma.sync.aligned.m16n8k8.row.col.f32.tf32.tf32.f32 "
                "{%0,%1,%2,%3}, {%4,%5,%6,%7}, {%8,%9}, {%0,%1,%2,%3};"
                : "+f"(acc[nt][0]), "+f"(acc[nt][1]),
                  "+f"(acc[nt][2]), "+f"(acc[nt][3])
                : "r"(__float_as_uint(a0)), "r"(__float_as_uint(a1)),
                  "r"(__float_as_uint(a2)), "r"(__float_as_uint(a3)),
                  "r"(__float_as_uint(b0)), "r"(__float_as_uint(b1)));
        }
    }

    int rowA = r0 + wr + g;
    int rowB = rowA + 8;
    #pragma unroll
    for (int nt = 0; nt < NTI; nt++) {
        int col = nt * 8 + 2 * tg;
        if (rowA < M)
            *reinterpret_cast<__half2*>(G + (size_t)rowA * BN + col) =
                __float22half2_rn(make_float2(acc[nt][0], acc[nt][1]));
        if (rowB < M)
            *reinterpret_cast<__half2*>(G + (size_t)rowB * BN + col) =
                __float22half2_rn(make_float2(acc[nt][2], acc[nt][3]));
    }
}

// ---- aggregation (R9 form + streaming hints) --------------------------------
// out[i] = relu(Σ wgt·g[src] + dinv²·g[i] + b); start = local offset + bpre
template <int F, typename OutT>
__global__ void __launch_bounds__(256)
k_agg(const __half* __restrict__ g, const float* __restrict__ bias,
      OutT* __restrict__ out, int n) {
    constexpr int V = F / 32;          // halfs per lane (4 or 2)
    int w = (blockIdx.x * blockDim.x + threadIdx.x) >> 5;
    if (w >= n) return;
    int lane = threadIdx.x & 31;

    float dv  = d_dinv[w];
    float dv2 = dv * dv;
    float acc[V];
    const __half* self = g + (size_t)w * F + lane * V;
    if constexpr (V == 4) {
        uint2 r = *reinterpret_cast<const uint2*>(self);
        float2 s0 = __half22float2(*reinterpret_cast<__half2*>(&r.x));
        float2 s1 = __half22float2(*reinterpret_cast<__half2*>(&r.y));
        acc[0] = s0.x * dv2; acc[1] = s0.y * dv2;
        acc[2] = s1.x * dv2; acc[3] = s1.y * dv2;
    } else {
        float2 s0 = __half22float2(*reinterpret_cast<const __half2*>(self));
        acc[0] = s0.x * dv2; acc[1] = s0.y * dv2;
    }

    int start = d_offsets[w] + d_bpre[w >> 10];   // local + block prefix
    int cnt   = d_counts[w];
    for (int j = 0; j < cnt; j += 8) {
        int2 ew[8];
        #pragma unroll
        for (int u = 0; u < 8; u++) ew[u] = __ldcs(&d_edge[start + j + u]);
        int   idx[8];
        float wf[8];
        #pragma unroll
        for (int u = 0; u < 8; u++) {
            bool ok = (j + u) < cnt;
            idx[u] = ok ? ew[u].x : w;
            wf[u]  = ok ? __int_as_float(ew[u].y) : 0.f;
        }
        if constexpr (V == 4) {
            uint2 t[8];
            #pragma unroll
            for (int u = 0; u < 8; u++)
                t[u] = *reinterpret_cast<const uint2*>(g + (size_t)idx[u] * F + lane * 4);
            #pragma unroll
            for (int u = 0; u < 8; u++) {
                float2 f0 = __half22float2(*reinterpret_cast<__half2*>(&t[u].x));
                float2 f1 = __half22float2(*reinterpret_cast<__half2*>(&t[u].y));
                acc[0] += f0.x * wf[u]; acc[1] += f0.y * wf[u];
                acc[2] += f1.x * wf[u]; acc[3] += f1.y * wf[u];
            }
        } else {
            unsigned t[8];
            #pragma unroll
            for (int u = 0; u < 8; u++)
                t[u] = *reinterpret_cast<const unsigned*>(g + (size_t)idx[u] * F + lane * 2);
            #pragma unroll
            for (int u = 0; u < 8; u++) {
                float2 f0 = __half22float2(*reinterpret_cast<__half2*>(&t[u]));
                acc[0] += f0.x * wf[u]; acc[1] += f0.y * wf[u];
            }
        }
    }

    float r[V];
    #pragma unroll
    for (int v = 0; v < V; v++) {
        float val = acc[v] + __ldg(&bias[lane * V + v]);
        r[v] = val > 0.f ? val : 0.f;
    }
    if constexpr (sizeof(OutT) == 4) {
        float* o = (float*)out + (size_t)w * F + lane * V;
        if constexpr (V == 4)
            __stcs(reinterpret_cast<float4*>(o), make_float4(r[0], r[1], r[2], r[3]));
        else
            __stcs(reinterpret_cast<float2*>(o), make_float2(r[0], r[1]));
    } else {
        __half* o = (__half*)out + (size_t)w * F + lane * V;
        if constexpr (V == 4) {
            uint2 p;
            *reinterpret_cast<__half2*>(&p.x) = __float22half2_rn(make_float2(r[0], r[1]));
            *reinterpret_cast<__half2*>(&p.y) = __float22half2_rn(make_float2(r[2], r[3]));
            __stcs(reinterpret_cast<uint2*>(o), p);
        } else {
            __half2 p = __float22half2_rn(make_float2(r[0], r[1]));
            __stcs(reinterpret_cast<unsigned*>(o), *reinterpret_cast<unsigned*>(&p));
        }
    }
}

// ---------------- launch -----------------------------------------------------
extern "C" void kernel_launch(void* const* d_in, const int* in_sizes, int n_in,
                              void* d_out, int out_size) {
    const float* x  = (const float*)d_in[0];
    const int*   ei = (const int*)d_in[1];
    const float* W1 = (const float*)d_in[2];
    const float* b1 = (const float*)d_in[3];
    const float* W2 = (const float*)d_in[4];
    const float* b2 = (const float*)d_in[5];
    float* out = (float*)d_out;

    const int M = in_sizes[0] / 128;  // 100000 nodes
    const int E = in_sizes[1] / 2;    // 1600000 edges

    constexpr int SMEM1 = (128 * 132 + 128 * (128 + 8)) * 4;  // 137216
    constexpr int SMEM2 = (64 * 132  + 128 * (64 + 8))  * 4;  // 70656

    __half *g1, *h1, *g2;
    int* counts;
    cudaGetSymbolAddress((void**)&g1, d_g1);
    cudaGetSymbolAddress((void**)&h1, d_h1);
    cudaGetSymbolAddress((void**)&g2, d_g2);
    cudaGetSymbolAddress((void**)&counts, d_counts);

    // one-time resource setup (identical captured graph every call)
    static cudaStream_t s1 = nullptr;
    static cudaEvent_t eFork = nullptr, eCsr = nullptr;
    if (!s1) {
        cudaStreamCreateWithFlags(&s1, cudaStreamNonBlocking);
        cudaEventCreateWithFlags(&eFork, cudaEventDisableTiming);
        cudaEventCreateWithFlags(&eCsr,  cudaEventDisableTiming);
        cudaFuncSetAttribute((const void*)k_gemm_tc<128, 128, float>,
                             cudaFuncAttributeMaxDynamicSharedMemorySize, SMEM1);
        cudaFuncSetAttribute((const void*)k_gemm_tc<64, 64, __half>,
                             cudaFuncAttributeMaxDynamicSharedMemorySize, SMEM2);
    }

    const int nblk = (M + 1023) / 1024;
    const int E4   = (E + 3) / 4;     // 4 edges per thread

    // fork: CSR build on s1 runs concurrently with GEMM1 on s0
    cudaEventRecord(eFork, 0);
    cudaStreamWaitEvent(s1, eFork, 0);

    cudaMemsetAsync(counts, 0, (size_t)M * sizeof(int), s1);
    k_count<<<(E4 + 255) / 256, 256, 0, s1>>>(ei, E);
    k_scan_local<<<nblk, 1024, 0, s1>>>(M);
    k_scan_bsum <<<1, 128, 0, s1>>>(nblk);
    k_fill <<<(E4 + 255) / 256, 256, 0, s1>>>(ei, E);
    cudaEventRecord(eCsr, s1);

    k_gemm_tc<128, 128, float><<<(M + 127) / 128, 256, SMEM1>>>(x, W1, g1, M);

    cudaStreamWaitEvent(0, eCsr, 0);   // join before agg1

    k_agg<128, __half><<<((M * 32) + 255) / 256, 256>>>(g1, b1, h1, M);
    k_gemm_tc<64, 64, __half><<<(M + 63) / 64, 128, SMEM2>>>(h1, W2, g2, M);
    k_agg<64, float><<<((M * 32) + 255) / 256, 256>>>(g2, b2, out, M);
}

// round 17
// speedup vs baseline: 1.0570x; 1.0330x over previous
#include <cuda_runtime.h>
#include <cuda_fp16.h>
#include <math.h>

#define NMAX 100000
#define EMAX 1600000
#define KDIM 128

// ---------------- scratch (static device globals; no allocation) ------------
__device__ __align__(16) __half d_g1[(size_t)NMAX * 128]; // x@W1  (fp16, gathered)
__device__ __align__(16) __half d_h1[(size_t)NMAX * 128]; // layer-1 out (fp16)
__device__ __align__(16) __half d_g2[(size_t)NMAX * 64];  // h1@W2 (fp16, gathered)
__device__ float d_dinv[NMAX];
__device__ int   d_counts[NMAX];
__device__ int   d_offsets[NMAX];   // block-LOCAL offsets (add d_bpre[i>>10])
__device__ int   d_cursor[NMAX];    // block-LOCAL cursors
__device__ int   d_bsum[128];
__device__ int   d_bpre[128];
__device__ __align__(16) int2 d_edge[EMAX + 16]; // (src, bitcast wgt); padded

// ---------------- CSR build (1 edge/thread: max atomic TLP) -----------------
__global__ void k_count(const int* __restrict__ ei, int E) {
    int e = blockIdx.x * blockDim.x + threadIdx.x;
    if (e < E) atomicAdd(&d_counts[ei[(size_t)E + e]], 1);
}

// stage 1: per-block (1024) local exclusive scan + dinv; cursor = local offset
__global__ void k_scan_local(int n) {
    __shared__ int wsum[32];
    int i    = blockIdx.x * 1024 + threadIdx.x;
    int lane = threadIdx.x & 31;
    int wid  = threadIdx.x >> 5;
    int v = (i < n) ? d_counts[i] : 0;
    int x = v;
    #pragma unroll
    for (int d = 1; d < 32; d <<= 1) {
        int t = __shfl_up_sync(0xffffffffu, x, d);
        if (lane >= d) x += t;
    }
    if (lane == 31) wsum[wid] = x;
    __syncthreads();
    if (wid == 0) {
        int s = wsum[lane];
        #pragma unroll
        for (int d = 1; d < 32; d <<= 1) {
            int t = __shfl_up_sync(0xffffffffu, s, d);
            if (lane >= d) s += t;
        }
        wsum[lane] = s;
    }
    __syncthreads();
    int warp_prefix = (wid > 0) ? wsum[wid - 1] : 0;
    if (i < n) {
        int loc = warp_prefix + x - v;
        d_offsets[i] = loc;               // local
        d_cursor[i]  = loc;               // local
        d_dinv[i]    = rsqrtf((float)(1 + v));
    }
    if (threadIdx.x == 1023) d_bsum[blockIdx.x] = warp_prefix + x;
}

// stage 2: scan the (<=128) block totals
__global__ void k_scan_bsum(int nb) {
    __shared__ int wsum[4];
    int lane = threadIdx.x & 31;
    int wid  = threadIdx.x >> 5;
    int v = (threadIdx.x < nb) ? d_bsum[threadIdx.x] : 0;
    int x = v;
    #pragma unroll
    for (int d = 1; d < 32; d <<= 1) {
        int t = __shfl_up_sync(0xffffffffu, x, d);
        if (lane >= d) x += t;
    }
    if (lane == 31) wsum[wid] = x;
    __syncthreads();
    int wp = 0;
    for (int k = 0; k < wid; k++) wp += wsum[k];
    if (threadIdx.x < nb) d_bpre[threadIdx.x] = wp + x - v;
}

// fill: 1 edge/thread; global pos = local cursor + block prefix
__global__ void k_fill(const int* __restrict__ ei, int E) {
    int e = blockIdx.x * blockDim.x + threadIdx.x;
    if (e < E) {
        int src = ei[e];
        int dst = ei[(size_t)E + e];
        int p = atomicAdd(&d_cursor[dst], 1) + d_bpre[dst >> 10];
        float wgt = d_dinv[src] * d_dinv[dst];
        d_edge[p] = make_int2(src, __float_as_int(wgt));
    }
}

// -------- tf32 tensor-core GEMM: G(half) = A[M,128] @ W[128,NW] -------------
// Block computes rows [bx*BM, +BM) x cols [by*BN, +BN) of G. NW = full width.
__device__ __forceinline__ float to_tf32(float x) {
    float r;
    asm("cvt.rna.tf32.f32 %0, %1;" : "=f"(r) : "f"(x));
    return r;
}

template <int BM, int BN, int NW, typename AT>
__global__ void __launch_bounds__(BM * 2)
k_gemm_tc(const AT* __restrict__ A, const float* __restrict__ W,
          __half* __restrict__ G, int M) {
    constexpr int K  = KDIM;
    constexpr int NT = BM * 2;
    constexpr int SA = 132;
    constexpr int SB = BN + 8;
    constexpr int NTI = BN / 8;

    extern __shared__ float sm[];
    float* As = sm;                  // [BM][SA]
    float* Ws = sm + BM * SA;        // [K][SB]

    const int tid  = threadIdx.x;
    const int r0   = blockIdx.x * BM;
    const int col0 = blockIdx.y * BN;

    if constexpr (sizeof(AT) == 4) {
        #pragma unroll
        for (int it = 0; it < (BM * (K / 4)) / NT; it++) {
            int i   = tid + it * NT;
            int row = i >> 5;
            int c4  = i & 31;
            float4 v = make_float4(0.f, 0.f, 0.f, 0.f);
            if (r0 + row < M)   // streaming read-once: evict-first
                v = __ldcs(reinterpret_cast<const float4*>((const float*)A + (size_t)(r0 + row) * K + c4 * 4));
            float* p = As + row * SA + c4 * 4;
            p[0] = to_tf32(v.x); p[1] = to_tf32(v.y);
            p[2] = to_tf32(v.z); p[3] = to_tf32(v.w);
        }
    } else {
        #pragma unroll
        for (int it = 0; it < (BM * (K / 8)) / NT; it++) {
            int i   = tid + it * NT;
            int row = i >> 4;
            int c8  = i & 15;
            uint4 v = make_uint4(0u, 0u, 0u, 0u);
            if (r0 + row < M)   // streaming read-once: evict-first
                v = __ldcs(reinterpret_cast<const uint4*>((const __half*)A + (size_t)(r0 + row) * K + c8 * 8));
            float2 f0 = __half22float2(*reinterpret_cast<__half2*>(&v.x));
            float2 f1 = __half22float2(*reinterpret_cast<__half2*>(&v.y));
            float2 f2 = __half22float2(*reinterpret_cast<__half2*>(&v.z));
            float2 f3 = __half22float2(*reinterpret_cast<__half2*>(&v.w));
            float* p = As + row * SA + c8 * 8;
            p[0] = to_tf32(f0.x); p[1] = to_tf32(f0.y);
            p[2] = to_tf32(f1.x); p[3] = to_tf32(f1.y);
            p[4] = to_tf32(f2.x); p[5] = to_tf32(f2.y);
            p[6] = to_tf32(f3.x); p[7] = to_tf32(f3.y);
        }
    }
    #pragma unroll
    for (int it = 0; it < (K * (BN / 4)) / NT; it++) {
        int i   = tid + it * NT;
        int row = i / (BN / 4);
        int c4  = i % (BN / 4);
        float4 v = *reinterpret_cast<const float4*>(W + (size_t)row * NW + col0 + c4 * 4);
        float* p = Ws + row * SB + c4 * 4;
        p[0] = to_tf32(v.x); p[1] = to_tf32(v.y);
        p[2] = to_tf32(v.z); p[3] = to_tf32(v.w);
    }
    __syncthreads();

    const int warp = tid >> 5;
    const int lane = tid & 31;
    const int g    = lane >> 2;
    const int tg   = lane & 3;
    const int wr   = warp * 16;

    float acc[NTI][4];
    #pragma unroll
    for (int nt = 0; nt < NTI; nt++) {
        acc[nt][0] = 0.f; acc[nt][1] = 0.f; acc[nt][2] = 0.f; acc[nt][3] = 0.f;
    }

    #pragma unroll
    for (int kc = 0; kc < K / 8; kc++) {
        int c = kc * 8 + tg;
        float a0 = As[(wr + g)     * SA + c];
        float a1 = As[(wr + g + 8) * SA + c];
        float a2 = As[(wr + g)     * SA + c + 4];
        float a3 = As[(wr + g + 8) * SA + c + 4];
        #pragma unroll
        for (int nt = 0; nt < NTI; nt++) {
            float b0 = Ws[c       * SB + nt * 8 + g];
            float b1 = Ws[(c + 4) * SB + nt * 8 + g];
            asm volatile(
                "mma.sync.aligned.m16n8k8.row.col.f32.tf32.tf32.f32 "
                "{%0,%1,%2,%3}, {%4,%5,%6,%7}, {%8,%9}, {%0,%1,%2,%3};"
                : "+f"(acc[nt][0]), "+f"(acc[nt][1]),
                  "+f"(acc[nt][2]), "+f"(acc[nt][3])
                : "r"(__float_as_uint(a0)), "r"(__float_as_uint(a1)),
                  "r"(__float_as_uint(a2)), "r"(__float_as_uint(a3)),
                  "r"(__float_as_uint(b0)), "r"(__float_as_uint(b1)));
        }
    }

    int rowA = r0 + wr + g;
    int rowB = rowA + 8;
    #pragma unroll
    for (int nt = 0; nt < NTI; nt++) {
        int col = col0 + nt * 8 + 2 * tg;
        if (rowA < M)
            *reinterpret_cast<__half2*>(G + (size_t)rowA * NW + col) =
                __float22half2_rn(make_float2(acc[nt][0], acc[nt][1]));
        if (rowB < M)
            *reinterpret_cast<__half2*>(G + (size_t)rowB * NW + col) =
                __float22half2_rn(make_float2(acc[nt][2], acc[nt][3]));
    }
}

// ---- aggregation (R9 form + streaming hints) --------------------------------
// out[i] = relu(Σ wgt·g[src] + dinv²·g[i] + b); start = local offset + bpre
template <int F, typename OutT>
__global__ void __launch_bounds__(256)
k_agg(const __half* __restrict__ g, const float* __restrict__ bias,
      OutT* __restrict__ out, int n) {
    constexpr int V = F / 32;          // halfs per lane (4 or 2)
    int w = (blockIdx.x * blockDim.x + threadIdx.x) >> 5;
    if (w >= n) return;
    int lane = threadIdx.x & 31;

    float dv  = d_dinv[w];
    float dv2 = dv * dv;
    float acc[V];
    const __half* self = g + (size_t)w * F + lane * V;
    if constexpr (V == 4) {
        uint2 r = *reinterpret_cast<const uint2*>(self);
        float2 s0 = __half22float2(*reinterpret_cast<__half2*>(&r.x));
        float2 s1 = __half22float2(*reinterpret_cast<__half2*>(&r.y));
        acc[0] = s0.x * dv2; acc[1] = s0.y * dv2;
        acc[2] = s1.x * dv2; acc[3] = s1.y * dv2;
    } else {
        float2 s0 = __half22float2(*reinterpret_cast<const __half2*>(self));
        acc[0] = s0.x * dv2; acc[1] = s0.y * dv2;
    }

    int start = d_offsets[w] + d_bpre[w >> 10];   // local + block prefix
    int cnt   = d_counts[w];
    for (int j = 0; j < cnt; j += 8) {
        int2 ew[8];
        #pragma unroll
        for (int u = 0; u < 8; u++) ew[u] = __ldcs(&d_edge[start + j + u]);
        int   idx[8];
        float wf[8];
        #pragma unroll
        for (int u = 0; u < 8; u++) {
            bool ok = (j + u) < cnt;
            idx[u] = ok ? ew[u].x : w;
            wf[u]  = ok ? __int_as_float(ew[u].y) : 0.f;
        }
        if constexpr (V == 4) {
            uint2 t[8];
            #pragma unroll
            for (int u = 0; u < 8; u++)
                t[u] = *reinterpret_cast<const uint2*>(g + (size_t)idx[u] * F + lane * 4);
            #pragma unroll
            for (int u = 0; u < 8; u++) {
                float2 f0 = __half22float2(*reinterpret_cast<__half2*>(&t[u].x));
                float2 f1 = __half22float2(*reinterpret_cast<__half2*>(&t[u].y));
                acc[0] += f0.x * wf[u]; acc[1] += f0.y * wf[u];
                acc[2] += f1.x * wf[u]; acc[3] += f1.y * wf[u];
            }
        } else {
            unsigned t[8];
            #pragma unroll
            for (int u = 0; u < 8; u++)
                t[u] = *reinterpret_cast<const unsigned*>(g + (size_t)idx[u] * F + lane * 2);
            #pragma unroll
            for (int u = 0; u < 8; u++) {
                float2 f0 = __half22float2(*reinterpret_cast<__half2*>(&t[u]));
                acc[0] += f0.x * wf[u]; acc[1] += f0.y * wf[u];
            }
        }
    }

    float r[V];
    #pragma unroll
    for (int v = 0; v < V; v++) {
        float val = acc[v] + __ldg(&bias[lane * V + v]);
        r[v] = val > 0.f ? val : 0.f;
    }
    if constexpr (sizeof(OutT) == 4) {
        float* o = (float*)out + (size_t)w * F + lane * V;
        if constexpr (V == 4)
            __stcs(reinterpret_cast<float4*>(o), make_float4(r[0], r[1], r[2], r[3]));
        else
            __stcs(reinterpret_cast<float2*>(o), make_float2(r[0], r[1]));
    } else {
        __half* o = (__half*)out + (size_t)w * F + lane * V;
        if constexpr (V == 4) {
            uint2 p;
            *reinterpret_cast<__half2*>(&p.x) = __float22half2_rn(make_float2(r[0], r[1]));
            *reinterpret_cast<__half2*>(&p.y) = __float22half2_rn(make_float2(r[2], r[3]));
            __stcs(reinterpret_cast<uint2*>(o), p);
        } else {
            __half2 p = __float22half2_rn(make_float2(r[0], r[1]));
            __stcs(reinterpret_cast<unsigned*>(o), *reinterpret_cast<unsigned*>(&p));
        }
    }
}

// ---------------- launch -----------------------------------------------------
extern "C" void kernel_launch(void* const* d_in, const int* in_sizes, int n_in,
                              void* d_out, int out_size) {
    const float* x  = (const float*)d_in[0];
    const int*   ei = (const int*)d_in[1];
    const float* W1 = (const float*)d_in[2];
    const float* b1 = (const float*)d_in[3];
    const float* W2 = (const float*)d_in[4];
    const float* b2 = (const float*)d_in[5];
    float* out = (float*)d_out;

    const int M = in_sizes[0] / 128;  // 100000 nodes
    const int E = in_sizes[1] / 2;    // 1600000 edges

    // GEMM1: BM=128, BN=64 (column-split, 2 blocks/SM). GEMM2: BM=64, BN=64.
    constexpr int SMEM1 = (128 * 132 + 128 * (64 + 8)) * 4;  // 104448
    constexpr int SMEM2 = (64 * 132  + 128 * (64 + 8)) * 4;  // 70656

    __half *g1, *h1, *g2;
    int* counts;
    cudaGetSymbolAddress((void**)&g1, d_g1);
    cudaGetSymbolAddress((void**)&h1, d_h1);
    cudaGetSymbolAddress((void**)&g2, d_g2);
    cudaGetSymbolAddress((void**)&counts, d_counts);

    // one-time resource setup (identical captured graph every call)
    static cudaStream_t s1 = nullptr;
    static cudaEvent_t eFork = nullptr, eCsr = nullptr;
    if (!s1) {
        cudaStreamCreateWithFlags(&s1, cudaStreamNonBlocking);
        cudaEventCreateWithFlags(&eFork, cudaEventDisableTiming);
        cudaEventCreateWithFlags(&eCsr,  cudaEventDisableTiming);
        cudaFuncSetAttribute((const void*)k_gemm_tc<128, 64, 128, float>,
                             cudaFuncAttributeMaxDynamicSharedMemorySize, SMEM1);
        cudaFuncSetAttribute((const void*)k_gemm_tc<64, 64, 64, __half>,
                             cudaFuncAttributeMaxDynamicSharedMemorySize, SMEM2);
    }

    const int nblk = (M + 1023) / 1024;

    // fork: CSR build on s1 runs concurrently with GEMM1 on s0
    cudaEventRecord(eFork, 0);
    cudaStreamWaitEvent(s1, eFork, 0);

    cudaMemsetAsync(counts, 0, (size_t)M * sizeof(int), s1);
    k_count<<<(E + 255) / 256, 256, 0, s1>>>(ei, E);
    k_scan_local<<<nblk, 1024, 0, s1>>>(M);
    k_scan_bsum <<<1, 128, 0, s1>>>(nblk);
    k_fill <<<(E + 255) / 256, 256, 0, s1>>>(ei, E);
    cudaEventRecord(eCsr, s1);

    {
        dim3 grid1((M + 127) / 128, 2);
        k_gemm_tc<128, 64, 128, float><<<grid1, 256, SMEM1>>>(x, W1, g1, M);
    }

    cudaStreamWaitEvent(0, eCsr, 0);   // join before agg1

    k_agg<128, __half><<<((M * 32) + 255) / 256, 256>>>(g1, b1, h1, M);
    k_gemm_tc<64, 64, 64, __half><<<(M + 63) / 64, 128, SMEM2>>>(h1, W2, g2, M);
    k_agg<64, float><<<((M * 32) + 255) / 256, 256>>>(g2, b2, out, M);
}